// round 16
// baseline (speedup 1.0000x reference)
#include <cuda_runtime.h>
#include <cuda_bf16.h>
#include <math.h>
#include <stdint.h>

// Problem dims (fixed by the dataset)
#define NN 8192
#define DD 1024
#define HH 4096
#define KK 4096   // codebook

// ---------------- scratch (static __device__, allocation-free) ----------------
__device__ float g_hcat[(size_t)NN * 2 * HH];   // [8192, 8192]
__device__ float g_h2[(size_t)NN * HH];         // [8192, 4096] (reused for scores)
__device__ float g_h3[(size_t)NN * HH];         // [8192, 4096]
__device__ float g_z[(size_t)NN * DD];          // [8192, 1024]
__device__ float g_e2[KK];
__device__ int   g_idx[NN];

// ---------------- packed f32x2 helpers ----------------
__device__ __forceinline__ void fma2(unsigned long long& c,
                                     unsigned long long a,
                                     unsigned long long b) {
    asm("fma.rn.f32x2 %0, %1, %2, %0;" : "+l"(c) : "l"(a), "l"(b));
}
__device__ __forceinline__ unsigned long long pack2(float lo, float hi) {
    unsigned long long r;
    asm("mov.b64 %0, {%1, %2};" : "=l"(r) : "f"(lo), "f"(hi));
    return r;
}
__device__ __forceinline__ float lo_f(unsigned long long v) {
    float lo, hi;
    asm("mov.b64 {%0, %1}, %2;" : "=f"(lo), "=f"(hi) : "l"(v));
    return lo;
}
__device__ __forceinline__ float hi_f(unsigned long long v) {
    float lo, hi;
    asm("mov.b64 {%0, %1}, %2;" : "=f"(lo), "=f"(hi) : "l"(v));
    return hi;
}

// ============================ FFMA2 GEMM (512 threads) ========================
// C[m,n] = act( sum_k A[m,k]*B[n,k] + bias[n] ),  A:[M,K], B:[N,K] row-major.
// CTA tile 256x128, 512 threads (16 warps -> 4 per SMSP), thread tile 8x8 held
// as 4 m-pairs x 8 cols. Same per-FMA LDS/issue ratios as the round-14 kernel
// but double the warps per scheduler to hide barrier/LDS/STS stalls.
// fma.rn.f32x2 = two independent IEEE fma.rn.f32 lanes; each output element
// keeps one accumulator with strictly ascending k -> bit-identical to rounds
// 1/7/9/10/13/14 (rel_err 6.29e-8).
#define BM 256
#define BN 128
#define BK 16
#define TM 8
#define TN 8

// ACT: 0=bias  1=fourier(bias+acc)  2=cat raw+fourier (ldc=2N)  3=score bias-2*acc
template <int ACT>
__global__ __launch_bounds__(512, 1)
void gemm_f2w(const float* __restrict__ A, const float* __restrict__ B,
              const float* __restrict__ bias, float* __restrict__ C,
              int M, int N, int K, int ldc)
{
    __shared__ float As[2][BK][BM];   // 32 KB
    __shared__ float Bs[2][BK][BN];   // 16 KB

    const int tid  = threadIdx.x;
    const int lane = tid & 31;
    const int wid  = tid >> 5;          // 0..15
    const int ty = lane >> 2;           // 0..7  (row groups of 8)
    const int tx = lane & 3;            // 0..3  (col groups of 8)
    const int wm = (wid >> 2) * 64;     // 4 warp-rows of 64
    const int wn = (wid & 3) * 32;      // 4 warp-cols of 32
    const int m0 = blockIdx.y * BM;
    const int n0 = blockIdx.x * BN;

    // loader mapping:
    //   A: 2 threads per row (256 rows), 8 k's (2 float4) each
    //   B: 4 threads per row (128 rows), 4 k's (1 float4) each
    const int alr = tid >> 1;           // 0..255
    const int alk = (tid & 1) * 8;      // 0 or 8
    const int blr = tid >> 2;           // 0..127
    const int blk = (tid & 3) * 4;      // 0,4,8,12
    const float* ag = A + (size_t)(m0 + alr) * K + alk;
    const float* bg = B + (size_t)(n0 + blr) * K + blk;

    const int nk = K / BK;

    // ---- prologue: LDG chunk0 -> STS stage0 ; LDG chunk1 -> regs ----
    float4 a0, a1, b0;
    a0 = *(const float4*)(ag);      a1 = *(const float4*)(ag + 4);
    b0 = *(const float4*)(bg);
    {
        As[0][alk + 0][alr] = a0.x; As[0][alk + 1][alr] = a0.y;
        As[0][alk + 2][alr] = a0.z; As[0][alk + 3][alr] = a0.w;
        As[0][alk + 4][alr] = a1.x; As[0][alk + 5][alr] = a1.y;
        As[0][alk + 6][alr] = a1.z; As[0][alk + 7][alr] = a1.w;
        Bs[0][blk + 0][blr] = b0.x; Bs[0][blk + 1][blr] = b0.y;
        Bs[0][blk + 2][blr] = b0.z; Bs[0][blk + 3][blr] = b0.w;
    }
    if (nk > 1) {
        a0 = *(const float4*)(ag + BK);      a1 = *(const float4*)(ag + BK + 4);
        b0 = *(const float4*)(bg + BK);
    }

    // acc pairs over M: acc2[p][j] = (acc[2p][j], acc[2p+1][j])
    unsigned long long acc2[TM / 2][TN];
#pragma unroll
    for (int p = 0; p < TM / 2; p++)
#pragma unroll
        for (int j = 0; j < TN; j++) acc2[p][j] = 0ull;

    for (int c = 0; c < nk; c++) {
        __syncthreads();   // STS(c) visible; stage (c+1)&1 free for writing

        const int s = (c + 1) & 1;                 // stage being filled
        const bool do_sts = (c + 1 < nk);
        const bool do_ldg = (c + 2 < nk);
        const float* an = ag + (size_t)(c + 2) * BK;   // LDG source (chunk c+2)
        const float* bn = bg + (size_t)(c + 2) * BK;

        const float (*as)[BM] = As[c & 1];
        const float (*bs)[BN] = Bs[c & 1];

        // ---- fragment double buffer: load kk=0 ----
        ulonglong2 au[2];
        float4     bu[2][2];
        ulonglong2 au2[2];
        {
            const float* ar = &as[0][wm + ty * TM];
            const float* br = &bs[0][wn + tx * TN];
            au[0]  = *(const ulonglong2*)(ar);
            au2[0] = *(const ulonglong2*)(ar + 4);
            bu[0][0] = *(const float4*)(br);
            bu[0][1] = *(const float4*)(br + 4);
        }

#pragma unroll
        for (int kk = 0; kk < BK; kk++) {
            const int cur = kk & 1;
            const int nxt = cur ^ 1;
            // prefetch kk+1 fragments (latency hidden under compute)
            if (kk + 1 < BK) {
                const float* ar = &as[kk + 1][wm + ty * TM];
                const float* br = &bs[kk + 1][wn + tx * TN];
                au[nxt]  = *(const ulonglong2*)(ar);
                au2[nxt] = *(const ulonglong2*)(ar + 4);
                bu[nxt][0] = *(const float4*)(br);
                bu[nxt][1] = *(const float4*)(br + 4);
            }

            // ---- compute kk ----
            unsigned long long Bd[TN];
            Bd[0] = pack2(bu[cur][0].x, bu[cur][0].x);
            Bd[1] = pack2(bu[cur][0].y, bu[cur][0].y);
            Bd[2] = pack2(bu[cur][0].z, bu[cur][0].z);
            Bd[3] = pack2(bu[cur][0].w, bu[cur][0].w);
            Bd[4] = pack2(bu[cur][1].x, bu[cur][1].x);
            Bd[5] = pack2(bu[cur][1].y, bu[cur][1].y);
            Bd[6] = pack2(bu[cur][1].z, bu[cur][1].z);
            Bd[7] = pack2(bu[cur][1].w, bu[cur][1].w);
            unsigned long long Ap[TM / 2];
            Ap[0] = au[cur].x;  Ap[1] = au[cur].y;
            Ap[2] = au2[cur].x; Ap[3] = au2[cur].y;
#pragma unroll
            for (int p = 0; p < TM / 2; p++)
#pragma unroll
                for (int j = 0; j < TN; j++)
                    fma2(acc2[p][j], Ap[p], Bd[j]);

            // ---- interleaved staging: retire one quad (STS then reload) ----
            if (kk == 1) {
                if (do_sts) {
                    As[s][alk + 0][alr] = a0.x; As[s][alk + 1][alr] = a0.y;
                    As[s][alk + 2][alr] = a0.z; As[s][alk + 3][alr] = a0.w;
                }
                if (do_ldg) a0 = *(const float4*)(an);
            } else if (kk == 5) {
                if (do_sts) {
                    As[s][alk + 4][alr] = a1.x; As[s][alk + 5][alr] = a1.y;
                    As[s][alk + 6][alr] = a1.z; As[s][alk + 7][alr] = a1.w;
                }
                if (do_ldg) a1 = *(const float4*)(an + 4);
            } else if (kk == 9) {
                if (do_sts) {
                    Bs[s][blk + 0][blr] = b0.x; Bs[s][blk + 1][blr] = b0.y;
                    Bs[s][blk + 2][blr] = b0.z; Bs[s][blk + 3][blr] = b0.w;
                }
                if (do_ldg) b0 = *(const float4*)(bn);
            }
        }
    }

    // ---- epilogue (identical expressions to rounds 1/7/9/10/13/14) ----
#pragma unroll
    for (int p = 0; p < TM / 2; p++) {
        const int me = m0 + wm + ty * TM + 2 * p;   // even row of the pair
        float* crow0 = C + (size_t)me * ldc;
        float* crow1 = C + (size_t)(me + 1) * ldc;
#pragma unroll
        for (int j = 0; j < TN; j++) {
            const int n = n0 + wn + tx * TN + j;
            const float s0 = lo_f(acc2[p][j]);   // row me
            const float s1 = hi_f(acc2[p][j]);   // row me+1
            if (ACT == 0) {
                crow0[n] = s0 + bias[n];
                crow1[n] = s1 + bias[n];
            } else if (ACT == 1) {
                const float v0 = s0 + bias[n];
                const float v1 = s1 + bias[n];
                crow0[n] = (n & 1) ? cosf(v0) : sinf(v0);
                crow1[n] = (n & 1) ? cosf(v1) : sinf(v1);
            } else if (ACT == 2) {
                const float v0 = s0 + bias[n];
                const float v1 = s1 + bias[n];
                crow0[n] = v0;
                crow1[n] = v1;
                crow0[N + n] = (n & 1) ? cosf(v0) : sinf(v0);
                crow1[N + n] = (n & 1) ? cosf(v1) : sinf(v1);
            } else { // 3: score
                crow0[n] = bias[n] - 2.0f * s0;
                crow1[n] = bias[n] - 2.0f * s1;
            }
        }
    }
}

// ---------------- e2[k] = ||emb[k]||^2 ----------------
__global__ void e2_kernel(const float* __restrict__ emb, float* __restrict__ e2)
{
    __shared__ float red[256];
    const int k = blockIdx.x;
    const float* row = emb + (size_t)k * DD;
    float s = 0.f;
    for (int d = threadIdx.x; d < DD; d += 256) { float v = row[d]; s += v * v; }
    red[threadIdx.x] = s;
    __syncthreads();
    for (int o = 128; o > 0; o >>= 1) {
        if (threadIdx.x < o) red[threadIdx.x] += red[threadIdx.x + o];
        __syncthreads();
    }
    if (threadIdx.x == 0) e2[k] = red[0];
}

// ---------------- per-row argmin over K scores (first-index tie-break) -------
__global__ void argmin_kernel(const float* __restrict__ scores, int* __restrict__ idx)
{
    __shared__ float bv[256];
    __shared__ int   bi[256];
    const int n = blockIdx.x;
    const float* row = scores + (size_t)n * KK;
    float best = 3.4e38f;
    int besti = 0;
    for (int k = threadIdx.x; k < KK; k += 256) {
        float v = row[k];
        if (v < best) { best = v; besti = k; }
    }
    bv[threadIdx.x] = best;
    bi[threadIdx.x] = besti;
    __syncthreads();
    for (int o = 128; o > 0; o >>= 1) {
        if (threadIdx.x < o) {
            float vo = bv[threadIdx.x + o];
            int   io = bi[threadIdx.x + o];
            if (vo < bv[threadIdx.x] ||
                (vo == bv[threadIdx.x] && io < bi[threadIdx.x])) {
                bv[threadIdx.x] = vo; bi[threadIdx.x] = io;
            }
        }
        __syncthreads();
    }
    if (threadIdx.x == 0) idx[n] = bi[0];
}

// ---------------- mueller hash (numpy int64 wraparound semantics) ------------
__device__ __forceinline__ long long mueller_hash(long long x)
{
    const unsigned long long C = 73244475ull;
    x = (long long)((unsigned long long)((x >> 16) ^ x) * C);
    x = (long long)((unsigned long long)((x >> 16) ^ x) * C);
    return (x >> 16) ^ x;
}

// ---------------- quantize: out[n] = sum_{i=1..3} emb[hash(idx+i*K)&(K-1)]/3 --
__global__ void quant_kernel(const float* __restrict__ emb,
                             const int* __restrict__ idx,
                             float* __restrict__ out)
{
    const int n = blockIdx.x;
    const long long id = (long long)idx[n];
    int s0 = (int)(mueller_hash(id + 1LL * KK) & (long long)(KK - 1));
    int s1 = (int)(mueller_hash(id + 2LL * KK) & (long long)(KK - 1));
    int s2 = (int)(mueller_hash(id + 3LL * KK) & (long long)(KK - 1));
    const float4* e0 = (const float4*)(emb + (size_t)s0 * DD);
    const float4* e1 = (const float4*)(emb + (size_t)s1 * DD);
    const float4* e2p = (const float4*)(emb + (size_t)s2 * DD);
    float4* o = (float4*)(out + (size_t)n * DD);
    const int d = threadIdx.x;
    float4 a = e0[d], b = e1[d], c = e2p[d];
    float4 r;
    r.x = (a.x / 3.0f + b.x / 3.0f) + c.x / 3.0f;
    r.y = (a.y / 3.0f + b.y / 3.0f) + c.y / 3.0f;
    r.z = (a.z / 3.0f + b.z / 3.0f) + c.z / 3.0f;
    r.w = (a.w / 3.0f + b.w / 3.0f) + c.w / 3.0f;
    o[d] = r;
}

// ---------------- host launcher ----------------
extern "C" void kernel_launch(void* const* d_in, const int* in_sizes, int n_in,
                              void* d_out, int out_size)
{
    const float* x   = (const float*)d_in[0];
    const float* w1  = (const float*)d_in[1];
    const float* b1  = (const float*)d_in[2];
    const float* w2  = (const float*)d_in[3];
    const float* b2  = (const float*)d_in[4];
    const float* w3  = (const float*)d_in[5];
    const float* b3  = (const float*)d_in[6];
    const float* w4  = (const float*)d_in[7];
    const float* b4  = (const float*)d_in[8];
    const float* emb = (const float*)d_in[9];
    float* out = (float*)d_out;

    float *hcat, *h2, *h3, *z, *e2d;
    int* idx;
    cudaGetSymbolAddress((void**)&hcat, g_hcat);
    cudaGetSymbolAddress((void**)&h2,   g_h2);
    cudaGetSymbolAddress((void**)&h3,   g_h3);
    cudaGetSymbolAddress((void**)&z,    g_z);
    cudaGetSymbolAddress((void**)&e2d,  g_e2);
    cudaGetSymbolAddress((void**)&idx,  g_idx);

    e2_kernel<<<KK, 256>>>(emb, e2d);

    // G1: hcat = [h1, fourier(h1)], h1 = x @ w1.T + b1
    gemm_f2w<2><<<dim3(HH / BN, NN / BM), 512>>>(x, w1, b1, hcat, NN, HH, DD, 2 * HH);
    // G2: h2 = fourier(hcat @ w2.T + b2)
    gemm_f2w<1><<<dim3(HH / BN, NN / BM), 512>>>(hcat, w2, b2, h2, NN, HH, 2 * HH, HH);
    // G3: h3 = fourier(h2 @ w3.T + b3)
    gemm_f2w<1><<<dim3(HH / BN, NN / BM), 512>>>(h2, w3, b3, h3, NN, HH, HH, HH);
    // G4: z = h3 @ w4.T + b4
    gemm_f2w<0><<<dim3(DD / BN, NN / BM), 512>>>(h3, w4, b4, z, NN, DD, HH, DD);
    // G5: scores = e2[k] - 2 * z @ emb.T  (reuse h2)
    gemm_f2w<3><<<dim3(KK / BN, NN / BM), 512>>>(z, emb, e2d, h2, NN, KK, DD, KK);

    argmin_kernel<<<NN, 256>>>(h2, idx);
    quant_kernel<<<NN, 256>>>(emb, idx, out);
}